// round 2
// baseline (speedup 1.0000x reference)
#include <cuda_runtime.h>
#include <cstdint>

#define BB   16
#define CIN  256
#define COUT 256
#define HH   64
#define WW   64
#define LAT  512

typedef unsigned long long ull;

// Scratch (device globals; no allocation allowed)
__device__ float g_s[BB * CIN];            // style affine output
__device__ float g_d[BB * COUT];           // demod scales
__device__ float g_wt[CIN * 9 * COUT];     // weight transposed: [ci][k][co]
__device__ float g_w2[COUT * CIN];         // sum_k weight^2 : [co][ci]

// ---------------------------------------------------------------------------
// s[b][ci] = style[b] @ style_w[:,ci] + style_b[ci]
__global__ void compute_s_kernel(const float* __restrict__ style,
                                 const float* __restrict__ style_w,
                                 const float* __restrict__ style_b) {
    int b = blockIdx.x;
    int ci = threadIdx.x;
    float acc = style_b[ci];
    const float* srow = style + b * LAT;
#pragma unroll 4
    for (int l = 0; l < LAT; ++l)
        acc = fmaf(srow[l], style_w[l * CIN + ci], acc);
    g_s[b * CIN + ci] = acc;
}

// ---------------------------------------------------------------------------
// Transpose weight -> g_wt[ci][k][co], and g_w2[co][ci] = sum_k w^2
__global__ void prep_w_kernel(const float* __restrict__ weight) {
    int idx = blockIdx.x * blockDim.x + threadIdx.x;  // 65536 total
    int co = idx & 255;
    int ci = idx >> 8;
    const float* wp = weight + (co * CIN + ci) * 9;
    float ssq = 0.f;
#pragma unroll
    for (int k = 0; k < 9; ++k) {
        float v = wp[k];
        ssq = fmaf(v, v, ssq);
        g_wt[(ci * 9 + k) * COUT + co] = v;
    }
    g_w2[co * CIN + ci] = ssq;
}

// ---------------------------------------------------------------------------
// d[b][co] = rsqrt( sum_ci s^2 * w2 + eps )
__global__ void compute_d_kernel() {
    int b = blockIdx.x;
    int co = threadIdx.x;
    const float* srow = g_s + b * CIN;
    const float* w2row = g_w2 + co * CIN;
    float acc = 0.f;
#pragma unroll 4
    for (int ci = 0; ci < CIN; ++ci) {
        float s = srow[ci];
        acc = fmaf(s * s, w2row[ci], acc);
    }
    g_d[b * COUT + co] = rsqrtf(acc + 1e-8f);
}

// ---------------------------------------------------------------------------
// Main conv: implicit GEMM, batch-shared weights, s folded into x on smem load,
// d/noise/bias/lrelu in epilogue. Packed f32x2 FFMA inner product.
//
// Block: 256 threads. Tile: 128 pixels (2 rows x 64 cols) x 128 couts.
// Thread tile: 8 pixels x 8 couts (as 8x4 packed f32x2 accumulators).
// K loop: 256 ci in chunks of 8, taps fully unrolled.
#define CI_CHUNK 8

__global__ __launch_bounds__(256) void conv_kernel(
    const float* __restrict__ x,
    const float* __restrict__ noise,
    const float* __restrict__ bias,
    const float* __restrict__ noise_weight,
    float* __restrict__ out)
{
    __shared__ __align__(16) float xs[CI_CHUNK][4][66];      // halo tile (scaled by s)
    __shared__ __align__(16) float ws[CI_CHUNK][9][128];     // weights [k][co]

    const int b = blockIdx.z;
    const int r0 = blockIdx.x * 2;            // first output row of tile
    const int co_base = blockIdx.y * 128;
    const int tid = threadIdx.x;
    const int tx = tid & 15;                  // pixel group
    const int ty = tid >> 4;                  // cout group

    ull acc[8][4] = {};                        // packed {f32,f32}, init 0.0f pairs

    const float* s_b = g_s + b * CIN;

    for (int ci0 = 0; ci0 < CIN; ci0 += CI_CHUNK) {
        __syncthreads();
        // ---- load x halo tile, scaled by s ----
#pragma unroll
        for (int l = 0; l < 9; ++l) {           // 9*256 = 2304 >= 2112
            int idx = tid + l * 256;
            if (idx < CI_CHUNK * 4 * 66) {
                int c   = idx % 66;
                int t   = idx / 66;
                int rr  = t & 3;
                int cil = t >> 2;
                int gr = r0 - 1 + rr;
                int gc = c - 1;
                int ci = ci0 + cil;
                float v = 0.f;
                if ((unsigned)gr < 64u && (unsigned)gc < 64u)
                    v = x[((b * CIN + ci) * HH + gr) * WW + gc] * s_b[ci];
                xs[cil][rr][c] = v;
            }
        }
        // ---- load weights (coalesced from pre-transposed g_wt) ----
#pragma unroll
        for (int l = 0; l < 36; ++l) {          // 36*256 = 9216
            int idx = tid + l * 256;
            int col = idx & 127;
            int k   = (idx >> 7) % 9;
            int cil = idx / (9 * 128);
            ws[cil][k][col] = g_wt[((ci0 + cil) * 9 + k) * COUT + co_base + col];
        }
        __syncthreads();

#pragma unroll 2
        for (int cil = 0; cil < CI_CHUNK; ++cil) {
#pragma unroll
            for (int ky = 0; ky < 3; ++ky) {
#pragma unroll
                for (int kx = 0; kx < 3; ++kx) {
                    // A: 8 pixel values, duplicated into both f32x2 lanes
                    ull ad[8];
#pragma unroll
                    for (int i = 0; i < 8; ++i) {
                        int p = tx + 16 * i;
                        int r = p >> 6;
                        int c = p & 63;
                        float a = xs[cil][r + ky][c + kx];
                        asm("mov.b64 %0, {%1, %1};" : "=l"(ad[i]) : "f"(a));
                    }
                    // B: 8 couts = 4 packed pairs (16B-aligned smem loads)
                    const ulonglong2* wp = reinterpret_cast<const ulonglong2*>(
                        &ws[cil][ky * 3 + kx][ty * 8]);
                    ulonglong2 b01 = wp[0];
                    ulonglong2 b23 = wp[1];
                    ull bp0 = b01.x, bp1 = b01.y, bp2 = b23.x, bp3 = b23.y;
#pragma unroll
                    for (int i = 0; i < 8; ++i) {
                        asm("fma.rn.f32x2 %0, %1, %2, %0;" : "+l"(acc[i][0]) : "l"(ad[i]), "l"(bp0));
                        asm("fma.rn.f32x2 %0, %1, %2, %0;" : "+l"(acc[i][1]) : "l"(ad[i]), "l"(bp1));
                        asm("fma.rn.f32x2 %0, %1, %2, %0;" : "+l"(acc[i][2]) : "l"(ad[i]), "l"(bp2));
                        asm("fma.rn.f32x2 %0, %1, %2, %0;" : "+l"(acc[i][3]) : "l"(ad[i]), "l"(bp3));
                    }
                }
            }
        }
    }

    // ---- epilogue: demod * acc + noise + bias, leaky relu * sqrt(2) ----
    const float nwv = noise_weight[0];
    const float* d_b = g_d + b * COUT;
#pragma unroll
    for (int i = 0; i < 8; ++i) {
        int p = tx + 16 * i;
        int r = r0 + (p >> 6);
        int c = p & 63;
        float nz = noise[(b * HH + r) * WW + c] * nwv;
#pragma unroll
        for (int j = 0; j < 4; ++j) {
            unsigned lo = (unsigned)(acc[i][j] & 0xffffffffull);
            unsigned hi = (unsigned)(acc[i][j] >> 32);
#pragma unroll
            for (int h = 0; h < 2; ++h) {
                int co = co_base + ty * 8 + 2 * j + h;
                float v = __uint_as_float(h ? hi : lo);
                v = v * d_b[co] + nz + bias[co];
                v = (v >= 0.f ? v : 0.2f * v) * 1.4142135623730951f;
                out[((b * COUT + co) * HH + r) * WW + c] = v;
            }
        }
    }
}

// ---------------------------------------------------------------------------
extern "C" void kernel_launch(void* const* d_in, const int* in_sizes, int n_in,
                              void* d_out, int out_size) {
    const float* x        = (const float*)d_in[0];
    const float* style    = (const float*)d_in[1];
    const float* noise    = (const float*)d_in[2];
    const float* weight   = (const float*)d_in[3];
    const float* style_w  = (const float*)d_in[4];
    const float* style_b  = (const float*)d_in[5];
    const float* bias     = (const float*)d_in[6];
    const float* nw       = (const float*)d_in[7];
    float* out = (float*)d_out;

    compute_s_kernel<<<BB, CIN>>>(style, style_w, style_b);
    prep_w_kernel<<<(COUT * CIN) / 256, 256>>>(weight);
    compute_d_kernel<<<BB, COUT>>>();
    conv_kernel<<<dim3(HH / 2, COUT / 128, BB), 256>>>(x, noise, bias, nw, out);
}

// round 4
// speedup vs baseline: 1.0007x; 1.0007x over previous
#include <cuda_runtime.h>
#include <cstdint>

#define BB   16
#define CIN  256
#define COUT 256
#define HH   64
#define WW   64
#define LAT  512

typedef unsigned long long ull;

// Scratch (device globals; no allocation allowed)
__device__ float g_s[BB * CIN];            // style affine output
__device__ float g_d[BB * COUT];           // demod scales
__device__ float g_wt[CIN * 9 * COUT];     // weight transposed: [ci][k][co]
__device__ float g_w2[COUT * CIN];         // sum_k weight^2 : [co][ci]

// ---------------------------------------------------------------------------
// s[b][ci] = style[b] @ style_w[:,ci] + style_b[ci]
__global__ void compute_s_kernel(const float* __restrict__ style,
                                 const float* __restrict__ style_w,
                                 const float* __restrict__ style_b) {
    int b = blockIdx.x;
    int ci = threadIdx.x;
    float acc = style_b[ci];
    const float* srow = style + b * LAT;
#pragma unroll 4
    for (int l = 0; l < LAT; ++l)
        acc = fmaf(srow[l], style_w[l * CIN + ci], acc);
    g_s[b * CIN + ci] = acc;
}

// ---------------------------------------------------------------------------
// Transpose weight -> g_wt[ci][k][co], and g_w2[co][ci] = sum_k w^2
__global__ void prep_w_kernel(const float* __restrict__ weight) {
    int idx = blockIdx.x * blockDim.x + threadIdx.x;  // 65536 total
    int co = idx & 255;
    int ci = idx >> 8;
    const float* wp = weight + (co * CIN + ci) * 9;
    float ssq = 0.f;
#pragma unroll
    for (int k = 0; k < 9; ++k) {
        float v = wp[k];
        ssq = fmaf(v, v, ssq);
        g_wt[(ci * 9 + k) * COUT + co] = v;
    }
    g_w2[co * CIN + ci] = ssq;
}

// ---------------------------------------------------------------------------
// d[b][co] = rsqrt( sum_ci s^2 * w2 + eps )
__global__ void compute_d_kernel() {
    int b = blockIdx.x;
    int co = threadIdx.x;
    const float* srow = g_s + b * CIN;
    const float* w2row = g_w2 + co * CIN;
    float acc = 0.f;
#pragma unroll 4
    for (int ci = 0; ci < CIN; ++ci) {
        float s = srow[ci];
        acc = fmaf(s * s, w2row[ci], acc);
    }
    g_d[b * COUT + co] = rsqrtf(acc + 1e-8f);
}

// ---------------------------------------------------------------------------
// Main conv: implicit GEMM, batch-shared weights, s folded into x on smem load,
// d/noise/bias/lrelu in epilogue. Packed f32x2 FFMA inner product.
//
// Block: 256 threads. Tile: 128 pixels (2 rows x 64 cols) x 128 couts.
// Thread tile: 8 pixels x 8 couts (as 8x4 packed f32x2 accumulators).
// K loop: 256 ci in chunks of 8, taps fully unrolled.
#define CI_CHUNK 8

__global__ __launch_bounds__(256) void conv_kernel(
    const float* __restrict__ x,
    const float* __restrict__ noise,
    const float* __restrict__ bias,
    const float* __restrict__ noise_weight,
    float* __restrict__ out)
{
    __shared__ __align__(16) float xs[CI_CHUNK][4][66];      // halo tile (scaled by s)
    __shared__ __align__(16) float ws[CI_CHUNK][9][128];     // weights [k][co]

    const int b = blockIdx.z;
    const int r0 = blockIdx.x * 2;            // first output row of tile
    const int co_base = blockIdx.y * 128;
    const int tid = threadIdx.x;
    const int tx = tid & 15;                  // pixel group
    const int ty = tid >> 4;                  // cout group

    ull acc[8][4] = {};                        // packed {f32,f32}, init 0.0f pairs

    const float* s_b = g_s + b * CIN;

    for (int ci0 = 0; ci0 < CIN; ci0 += CI_CHUNK) {
        __syncthreads();
        // ---- load x halo tile, scaled by s ----
#pragma unroll
        for (int l = 0; l < 9; ++l) {           // 9*256 = 2304 >= 2112
            int idx = tid + l * 256;
            if (idx < CI_CHUNK * 4 * 66) {
                int c   = idx % 66;
                int t   = idx / 66;
                int rr  = t & 3;
                int cil = t >> 2;
                int gr = r0 - 1 + rr;
                int gc = c - 1;
                int ci = ci0 + cil;
                float v = 0.f;
                if ((unsigned)gr < 64u && (unsigned)gc < 64u)
                    v = x[((b * CIN + ci) * HH + gr) * WW + gc] * s_b[ci];
                xs[cil][rr][c] = v;
            }
        }
        // ---- load weights (coalesced from pre-transposed g_wt) ----
#pragma unroll
        for (int l = 0; l < 36; ++l) {          // 36*256 = 9216
            int idx = tid + l * 256;
            int col = idx & 127;
            int k   = (idx >> 7) % 9;
            int cil = idx / (9 * 128);
            ws[cil][k][col] = g_wt[((ci0 + cil) * 9 + k) * COUT + co_base + col];
        }
        __syncthreads();

#pragma unroll 2
        for (int cil = 0; cil < CI_CHUNK; ++cil) {
#pragma unroll
            for (int ky = 0; ky < 3; ++ky) {
#pragma unroll
                for (int kx = 0; kx < 3; ++kx) {
                    // A: 8 pixel values, duplicated into both f32x2 lanes
                    ull ad[8];
#pragma unroll
                    for (int i = 0; i < 8; ++i) {
                        int p = tx + 16 * i;
                        int r = p >> 6;
                        int c = p & 63;
                        float a = xs[cil][r + ky][c + kx];
                        asm("mov.b64 %0, {%1, %1};" : "=l"(ad[i]) : "f"(a));
                    }
                    // B: 8 couts = 4 packed pairs (16B-aligned smem loads)
                    const ulonglong2* wp = reinterpret_cast<const ulonglong2*>(
                        &ws[cil][ky * 3 + kx][ty * 8]);
                    ulonglong2 b01 = wp[0];
                    ulonglong2 b23 = wp[1];
                    ull bp0 = b01.x, bp1 = b01.y, bp2 = b23.x, bp3 = b23.y;
#pragma unroll
                    for (int i = 0; i < 8; ++i) {
                        asm("fma.rn.f32x2 %0, %1, %2, %0;" : "+l"(acc[i][0]) : "l"(ad[i]), "l"(bp0));
                        asm("fma.rn.f32x2 %0, %1, %2, %0;" : "+l"(acc[i][1]) : "l"(ad[i]), "l"(bp1));
                        asm("fma.rn.f32x2 %0, %1, %2, %0;" : "+l"(acc[i][2]) : "l"(ad[i]), "l"(bp2));
                        asm("fma.rn.f32x2 %0, %1, %2, %0;" : "+l"(acc[i][3]) : "l"(ad[i]), "l"(bp3));
                    }
                }
            }
        }
    }

    // ---- epilogue: demod * acc + noise + bias, leaky relu * sqrt(2) ----
    const float nwv = noise_weight[0];
    const float* d_b = g_d + b * COUT;
#pragma unroll
    for (int i = 0; i < 8; ++i) {
        int p = tx + 16 * i;
        int r = r0 + (p >> 6);
        int c = p & 63;
        float nz = noise[(b * HH + r) * WW + c] * nwv;
#pragma unroll
        for (int j = 0; j < 4; ++j) {
            unsigned lo = (unsigned)(acc[i][j] & 0xffffffffull);
            unsigned hi = (unsigned)(acc[i][j] >> 32);
#pragma unroll
            for (int h = 0; h < 2; ++h) {
                int co = co_base + ty * 8 + 2 * j + h;
                float v = __uint_as_float(h ? hi : lo);
                v = v * d_b[co] + nz + bias[co];
                v = (v >= 0.f ? v : 0.2f * v) * 1.4142135623730951f;
                out[((b * COUT + co) * HH + r) * WW + c] = v;
            }
        }
    }
}

// ---------------------------------------------------------------------------
extern "C" void kernel_launch(void* const* d_in, const int* in_sizes, int n_in,
                              void* d_out, int out_size) {
    const float* x        = (const float*)d_in[0];
    const float* style    = (const float*)d_in[1];
    const float* noise    = (const float*)d_in[2];
    const float* weight   = (const float*)d_in[3];
    const float* style_w  = (const float*)d_in[4];
    const float* style_b  = (const float*)d_in[5];
    const float* bias     = (const float*)d_in[6];
    const float* nw       = (const float*)d_in[7];
    float* out = (float*)d_out;

    compute_s_kernel<<<BB, CIN>>>(style, style_w, style_b);
    prep_w_kernel<<<(COUT * CIN) / 256, 256>>>(weight);
    compute_d_kernel<<<BB, COUT>>>();
    conv_kernel<<<dim3(HH / 2, COUT / 128, BB), 256>>>(x, noise, bias, nw, out);
}

// round 7
// speedup vs baseline: 4.9942x; 4.9905x over previous
#include <cuda_runtime.h>
#include <cuda_fp16.h>
#include <cstdint>
#include <cstddef>

#define BB   16
#define CIN  256
#define COUT 256
#define HH   64
#define WW   64
#define LATD 512

typedef unsigned long long ull;

// ---------------- device scratch (no allocation allowed) ----------------
__device__ float g_s[BB * CIN];
__device__ float g_d[BB * COUT];
__device__ float g_w2[COUT * CIN];
// weights fp16: [tap][cic][co 0..255][64 ci]
__device__ __half g_wf[9 * 4 * 256 * 64];
// modulated x fp16, pixel-major: [b][h][w][ci]
__device__ __half g_xm[(size_t)BB * HH * WW * CIN];

// ---------------- prep kernels ----------------
__global__ void compute_s_kernel(const float* __restrict__ style,
                                 const float* __restrict__ style_w,
                                 const float* __restrict__ style_b) {
    int b = blockIdx.x, ci = threadIdx.x;
    float acc = style_b[ci];
    const float* srow = style + b * LATD;
#pragma unroll 4
    for (int l = 0; l < LATD; ++l)
        acc = fmaf(srow[l], style_w[l * CIN + ci], acc);
    g_s[b * CIN + ci] = acc;
}

__global__ void wprep_kernel(const float* __restrict__ weight) {
    int co = blockIdx.x, ci = threadIdx.x;
    const float* wp = weight + (co * CIN + ci) * 9;
    int cic = ci >> 6, cil = ci & 63;
    float ssq = 0.f;
#pragma unroll
    for (int k = 0; k < 9; ++k) {
        float v = wp[k];
        ssq = fmaf(v, v, ssq);
        g_wf[((size_t)(k * 4 + cic) * 256 + co) * 64 + cil] = __float2half_rn(v);
    }
    g_w2[co * CIN + ci] = ssq;
}

__global__ void compute_d_kernel() {
    int b = blockIdx.x, co = threadIdx.x;
    const float* srow = g_s + b * CIN;
    const float* w2row = g_w2 + co * CIN;
    float acc = 0.f;
#pragma unroll 4
    for (int ci = 0; ci < CIN; ++ci) {
        float s = srow[ci];
        acc = fmaf(s * s, w2row[ci], acc);
    }
    g_d[b * COUT + co] = rsqrtf(acc + 1e-8f);
}

// transpose + modulate: x[b][ci][h][w] fp32 -> g_xm[b][h][w][ci] fp16
#define TP 266
__global__ void xconv_kernel(const float* __restrict__ x) {
    __shared__ unsigned short smt[64 * TP];
    int h = blockIdx.x & 63;
    int b = blockIdx.x >> 6;
    int t = threadIdx.x;
#pragma unroll
    for (int j = 0; j < 64; ++j) {
        int idx = t + 256 * j;             // 16384 = 256ci * 64w
        int ci = idx >> 6, w = idx & 63;
        float v = x[((size_t)(b * CIN + ci) * HH + h) * WW + w] * g_s[b * CIN + ci];
        smt[w * TP + ci] = __half_as_ushort(__float2half_rn(v));
    }
    __syncthreads();
    int w = t >> 2, q = t & 3;
    uint4* dst = (uint4*)(g_xm + (((size_t)(b * HH + h)) * WW + w) * CIN + q * 64);
#pragma unroll
    for (int j = 0; j < 8; ++j) {
        const uint32_t* p32 = (const uint32_t*)&smt[w * TP + q * 64 + j * 8];
        uint4 v;
        v.x = p32[0]; v.y = p32[1]; v.z = p32[2]; v.w = p32[3];
        dst[j] = v;
    }
}

// ---------------- ptx helpers ----------------
static __device__ __forceinline__ uint32_t s2u(const void* p) {
    uint32_t a;
    asm("{ .reg .u64 t; cvta.to.shared.u64 t, %1; cvt.u32.u64 %0, t; }" : "=r"(a) : "l"(p));
    return a;
}
#define CPASYNC(dst, src, sz) \
    asm volatile("cp.async.cg.shared.global [%0], [%1], 16, %2;" \
                 :: "r"(dst), "l"(src), "r"(sz))
#define CPCOMMIT() asm volatile("cp.async.commit_group;")
#define CPWAIT2()  asm volatile("cp.async.wait_group 2;")
#define LDSM4(r0, r1, r2, r3, a) \
    asm volatile("ldmatrix.sync.aligned.m8n8.x4.shared.b16 {%0,%1,%2,%3}, [%4];" \
                 : "=r"(r0), "=r"(r1), "=r"(r2), "=r"(r3) : "r"(a))
#define MMA16816(c, a, b0, b1) \
    asm volatile("mma.sync.aligned.m16n8k16.row.col.f32.f16.f16.f32 " \
                 "{%0,%1,%2,%3}, {%4,%5,%6,%7}, {%8,%9}, {%0,%1,%2,%3};" \
                 : "+f"((c)[0]), "+f"((c)[1]), "+f"((c)[2]), "+f"((c)[3]) \
                 : "r"((a)[0]), "r"((a)[1]), "r"((a)[2]), "r"((a)[3]), "r"(b0), "r"(b1))

// ---------------- main conv kernel ----------------
// smem: 3 stages x 32KB (A 16KB @ +0, B 16KB @ +16384); nzs @ 98304
#define ST_SZ    32768
#define SM_NZ    98304
#define SMEM_REQ (SM_NZ + 512)

// load one (tap,cic) chunk into stage st
static __device__ __forceinline__ void load_chunk(uint32_t smb, int st, int idx,
                                                  int b, int r0, int co_base, int tid) {
    const int tap = idx >> 2, cic = idx & 3;
    const int dy = tap / 3 - 1, dx = tap % 3 - 1;
    const uint32_t base = smb + st * ST_SZ;
    // A: 128 px rows x 64 ci (fp16) = 16KB
#pragma unroll
    for (int j = 0; j < 4; ++j) {
        int lin = tid + j * 256;
        int p = lin >> 3, c8 = lin & 7;
        int h = r0 + (p >> 6) + dy;
        int w = (p & 63) + dx;
        bool ok = ((unsigned)h < 64u) && ((unsigned)w < 64u);
        const __half* src = ok
            ? g_xm + (((size_t)(b * HH + h)) * WW + w) * CIN + cic * 64 + c8 * 8
            : g_xm;
        int sz = ok ? 16 : 0;
        uint32_t off = p * 128 + c8 * 16;
        CPASYNC(base + (off ^ ((off >> 3) & 0x70)), src, sz);
    }
    // B: 128 co rows x 64 ci = 16KB
#pragma unroll
    for (int j = 0; j < 4; ++j) {
        int lin = tid + j * 256;
        int p = lin >> 3, c8 = lin & 7;
        const __half* src = g_wf +
            ((size_t)(tap * 4 + cic) * 256 + co_base + p) * 64 + c8 * 8;
        uint32_t off = p * 128 + c8 * 16;
        CPASYNC(base + 16384 + (off ^ ((off >> 3) & 0x70)), src, 16);
    }
    CPCOMMIT();
}

__global__ void __launch_bounds__(256) conv_mma_kernel(
    const float* __restrict__ noise,
    const float* __restrict__ bias,
    const float* __restrict__ nwp,
    float* __restrict__ out)
{
    extern __shared__ __align__(1024) char sm[];
    const uint32_t smb = s2u(sm);
    const int tid = threadIdx.x;
    const int lane = tid & 31, wid = tid >> 5;
    const int mw = wid & 1, nw = wid >> 1;
    const int r0 = blockIdx.x * 2;           // image rows [r0, r0+1]
    const int co_base = blockIdx.y * 128;
    const int b = blockIdx.z;

    // stage scaled noise
    float* nzs = (float*)(sm + SM_NZ);
    if (tid < 128)
        nzs[tid] = noise[(b * HH + r0 + (tid >> 6)) * WW + (tid & 63)] * nwp[0];

    // lane-constant address pieces
    const int rA = mw * 64 + (lane & 15);
    const int hiA = lane >> 4;
    const int rB = nw * 32 + (lane & 7) + ((lane >> 4) & 1) * 8;
    const int hiB = (lane >> 3) & 1;
    const int sx = lane & 7;

    float c[4][4][4] = {};

    // prologue: chunks 0, 1
    load_chunk(smb, 0, 0, b, r0, co_base, tid);
    load_chunk(smb, 1, 1, b, r0, co_base, tid);

    for (int i = 0; i < 36; ++i) {
        if (i + 2 < 36) load_chunk(smb, (i + 2) % 3, i + 2, b, r0, co_base, tid);
        else CPCOMMIT();                       // keep group count in lockstep
        CPWAIT2();
        __syncthreads();

        const uint32_t stA = smb + (i % 3) * ST_SZ;
        const uint32_t stB = stA + 16384;
#pragma unroll
        for (int ks = 0; ks < 4; ++ks) {
            uint32_t a[4][4], bw[4][2];
#pragma unroll
            for (int mi = 0; mi < 4; ++mi) {
                uint32_t ad = stA + (rA + mi * 16) * 128
                            + (((ks * 2 + hiA) ^ sx) << 4);
                LDSM4(a[mi][0], a[mi][1], a[mi][2], a[mi][3], ad);
            }
#pragma unroll
            for (int g = 0; g < 2; ++g) {
                uint32_t bd = stB + (rB + g * 16) * 128
                            + (((ks * 2 + hiB) ^ sx) << 4);
                LDSM4(bw[2 * g][0], bw[2 * g][1], bw[2 * g + 1][0], bw[2 * g + 1][1], bd);
            }
#pragma unroll
            for (int mi = 0; mi < 4; ++mi)
#pragma unroll
                for (int ni = 0; ni < 4; ++ni)
                    MMA16816(c[mi][ni], a[mi], bw[ni][0], bw[ni][1]);
        }
        __syncthreads();
    }

    // ---- epilogue: regs -> smem transpose (pitch 129) -> fused stores ----
    float* smo = (float*)sm;
#pragma unroll
    for (int mi = 0; mi < 4; ++mi) {
        int row = mw * 64 + mi * 16 + (lane >> 2);
#pragma unroll
        for (int ni = 0; ni < 4; ++ni) {
            int col = nw * 32 + ni * 8 + 2 * (lane & 3);
            smo[row * 129 + col]           = c[mi][ni][0];
            smo[row * 129 + col + 1]       = c[mi][ni][1];
            smo[(row + 8) * 129 + col]     = c[mi][ni][2];
            smo[(row + 8) * 129 + col + 1] = c[mi][ni][3];
        }
    }
    __syncthreads();

    const int p = tid & 127;
    const int hrow = r0 + (p >> 6), wcol = p & 63;
    const float nz = nzs[p];
#pragma unroll 4
    for (int kk = 0; kk < 64; ++kk) {
        int co_l = (tid >> 7) + kk * 2;
        int co = co_base + co_l;
        float v = smo[p * 129 + co_l];
        v = v * g_d[b * COUT + co] + nz + bias[co];
        v = (v >= 0.f ? v : 0.2f * v) * 1.4142135623730951f;
        out[((size_t)(b * COUT + co) * HH + hrow) * WW + wcol] = v;
    }
}

// ---------------------------------------------------------------------------
extern "C" void kernel_launch(void* const* d_in, const int* in_sizes, int n_in,
                              void* d_out, int out_size) {
    const float* x       = (const float*)d_in[0];
    const float* style   = (const float*)d_in[1];
    const float* noise   = (const float*)d_in[2];
    const float* weight  = (const float*)d_in[3];
    const float* style_w = (const float*)d_in[4];
    const float* style_b = (const float*)d_in[5];
    const float* bias    = (const float*)d_in[6];
    const float* nw      = (const float*)d_in[7];
    float* out = (float*)d_out;

    cudaFuncSetAttribute(conv_mma_kernel,
                         cudaFuncAttributeMaxDynamicSharedMemorySize, SMEM_REQ);

    compute_s_kernel<<<BB, CIN>>>(style, style_w, style_b);
    wprep_kernel<<<COUT, CIN>>>(weight);
    compute_d_kernel<<<BB, COUT>>>();
    xconv_kernel<<<BB * HH, 256>>>(x);
    conv_mma_kernel<<<dim3(HH / 2, COUT / 128, BB), 256, SMEM_REQ>>>(noise, bias, nw, out);
}

// round 9
// speedup vs baseline: 5.0730x; 1.0158x over previous
#include <cuda_runtime.h>
#include <cuda_fp16.h>
#include <cstdint>
#include <cstddef>

#define BB   16
#define CIN  256
#define COUT 256
#define HH   64
#define WW   64
#define LATD 512

typedef unsigned long long ull;

// ---------------- device scratch (no allocation allowed) ----------------
__device__ float g_s[BB * CIN];
__device__ float g_d[BB * COUT];
__device__ float g_w2[COUT * CIN];
// weights fp16: [tap][cic][co 0..255][64 ci]
__device__ __half g_wf[9 * 4 * 256 * 64];
// modulated x fp16, pixel-major: [b][h][w][ci]
__device__ __half g_xm[(size_t)BB * HH * WW * CIN];

// ---------------- prep kernels ----------------
__global__ void compute_s_kernel(const float* __restrict__ style,
                                 const float* __restrict__ style_w,
                                 const float* __restrict__ style_b) {
    int b = blockIdx.x, ci = threadIdx.x;
    float acc = style_b[ci];
    const float* srow = style + b * LATD;
#pragma unroll 4
    for (int l = 0; l < LATD; ++l)
        acc = fmaf(srow[l], style_w[l * CIN + ci], acc);
    g_s[b * CIN + ci] = acc;
}

__global__ void wprep_kernel(const float* __restrict__ weight) {
    int co = blockIdx.x, ci = threadIdx.x;
    const float* wp = weight + (co * CIN + ci) * 9;
    int cic = ci >> 6, cil = ci & 63;
    float ssq = 0.f;
#pragma unroll
    for (int k = 0; k < 9; ++k) {
        float v = wp[k];
        ssq = fmaf(v, v, ssq);
        g_wf[((size_t)(k * 4 + cic) * 256 + co) * 64 + cil] = __float2half_rn(v);
    }
    g_w2[co * CIN + ci] = ssq;
}

__global__ void compute_d_kernel() {
    int b = blockIdx.x, co = threadIdx.x;
    const float* srow = g_s + b * CIN;
    const float* w2row = g_w2 + co * CIN;
    float acc = 0.f;
#pragma unroll 4
    for (int ci = 0; ci < CIN; ++ci) {
        float s = srow[ci];
        acc = fmaf(s * s, w2row[ci], acc);
    }
    g_d[b * COUT + co] = rsqrtf(acc + 1e-8f);
}

// transpose + modulate: x[b][ci][h][w] fp32 -> g_xm[b][h][w][ci] fp16
#define TP 266
__global__ void xconv_kernel(const float4* __restrict__ x4) {
    __shared__ unsigned short smt[64 * TP];
    int h = blockIdx.x & 63;
    int b = blockIdx.x >> 6;
    int t = threadIdx.x;
    // phase 1: vectorized coalesced read (float4), modulate, scatter to smem
#pragma unroll
    for (int j = 0; j < 16; ++j) {
        int idx = t + 256 * j;               // 4096 float4 = 256ci * 16 groups
        int ci = idx >> 4;
        int g = idx & 15;                    // group of 4 w's
        float s = g_s[b * CIN + ci];
        float4 v = x4[((size_t)(b * CIN + ci) * HH + h) * 16 + g];
        int w = g * 4;
        smt[(w + 0) * TP + ci] = __half_as_ushort(__float2half_rn(v.x * s));
        smt[(w + 1) * TP + ci] = __half_as_ushort(__float2half_rn(v.y * s));
        smt[(w + 2) * TP + ci] = __half_as_ushort(__float2half_rn(v.z * s));
        smt[(w + 3) * TP + ci] = __half_as_ushort(__float2half_rn(v.w * s));
    }
    __syncthreads();
    // phase 2: coalesced 128-bit writes
    int w = t >> 2, q = t & 3;
    uint4* dst = (uint4*)(g_xm + (((size_t)(b * HH + h)) * WW + w) * CIN + q * 64);
#pragma unroll
    for (int j = 0; j < 8; ++j) {
        const uint32_t* p32 = (const uint32_t*)&smt[w * TP + q * 64 + j * 8];
        uint4 v;
        v.x = p32[0]; v.y = p32[1]; v.z = p32[2]; v.w = p32[3];
        dst[j] = v;
    }
}

// ---------------- ptx helpers ----------------
static __device__ __forceinline__ uint32_t s2u(const void* p) {
    uint32_t a;
    asm("{ .reg .u64 t; cvta.to.shared.u64 t, %1; cvt.u32.u64 %0, t; }" : "=r"(a) : "l"(p));
    return a;
}
#define CPASYNC(dst, src, sz) \
    asm volatile("cp.async.cg.shared.global [%0], [%1], 16, %2;" \
                 :: "r"(dst), "l"(src), "r"(sz))
#define CPCOMMIT() asm volatile("cp.async.commit_group;")
#define CPWAIT2()  asm volatile("cp.async.wait_group 2;")
#define LDSM4(r0, r1, r2, r3, a) \
    asm volatile("ldmatrix.sync.aligned.m8n8.x4.shared.b16 {%0,%1,%2,%3}, [%4];" \
                 : "=r"(r0), "=r"(r1), "=r"(r2), "=r"(r3) : "r"(a))
#define MMA16816(c, a, b0, b1) \
    asm volatile("mma.sync.aligned.m16n8k16.row.col.f32.f16.f16.f32 " \
                 "{%0,%1,%2,%3}, {%4,%5,%6,%7}, {%8,%9}, {%0,%1,%2,%3};" \
                 : "+f"((c)[0]), "+f"((c)[1]), "+f"((c)[2]), "+f"((c)[3]) \
                 : "r"((a)[0]), "r"((a)[1]), "r"((a)[2]), "r"((a)[3]), "r"(b0), "r"(b1))

// ---------------- main conv kernel ----------------
// smem: 3 stages x 32KB (A 16KB @ +0, B 16KB @ +16384). Epilogue reuses stage mem.
#define ST_SZ    32768
#define SMEM_REQ (3 * ST_SZ)

// load one (tap,cic) chunk into stage st
static __device__ __forceinline__ void load_chunk(uint32_t smb, int st, int idx,
                                                  int b, int r0, int co_base, int tid) {
    const int tap = idx >> 2, cic = idx & 3;
    const int dy = tap / 3 - 1, dx = tap % 3 - 1;
    const uint32_t base = smb + st * ST_SZ;
    // A: 128 px rows x 64 ci (fp16) = 16KB
#pragma unroll
    for (int j = 0; j < 4; ++j) {
        int lin = tid + j * 256;
        int p = lin >> 3, c8 = lin & 7;
        int h = r0 + (p >> 6) + dy;
        int w = (p & 63) + dx;
        bool ok = ((unsigned)h < 64u) && ((unsigned)w < 64u);
        const __half* src = ok
            ? g_xm + (((size_t)(b * HH + h)) * WW + w) * CIN + cic * 64 + c8 * 8
            : g_xm;
        int sz = ok ? 16 : 0;
        uint32_t off = p * 128 + c8 * 16;
        CPASYNC(base + (off ^ ((off >> 3) & 0x70)), src, sz);
    }
    // B: 128 co rows x 64 ci = 16KB
#pragma unroll
    for (int j = 0; j < 4; ++j) {
        int lin = tid + j * 256;
        int p = lin >> 3, c8 = lin & 7;
        const __half* src = g_wf +
            ((size_t)(tap * 4 + cic) * 256 + co_base + p) * 64 + c8 * 8;
        uint32_t off = p * 128 + c8 * 16;
        CPASYNC(base + 16384 + (off ^ ((off >> 3) & 0x70)), src, 16);
    }
    CPCOMMIT();
}

__global__ void __launch_bounds__(256, 2) conv_mma_kernel(
    const float* __restrict__ noise,
    const float* __restrict__ bias,
    const float* __restrict__ nwp,
    float* __restrict__ out)
{
    extern __shared__ __align__(1024) char sm[];
    const uint32_t smb = s2u(sm);
    const int tid = threadIdx.x;
    const int lane = tid & 31, wid = tid >> 5;
    const int mw = wid & 1, nw = wid >> 1;
    const int r0 = blockIdx.x * 2;           // image rows [r0, r0+1]
    const int co_base = blockIdx.y * 128;
    const int b = blockIdx.z;

    // lane-constant address pieces
    const int rA = mw * 64 + (lane & 15);
    const int hiA = lane >> 4;
    const int rB = nw * 32 + (lane & 7) + ((lane >> 4) & 1) * 8;
    const int hiB = (lane >> 3) & 1;
    const int sx = lane & 7;

    float c[4][4][4] = {};

    // prologue: chunks 0, 1
    load_chunk(smb, 0, 0, b, r0, co_base, tid);
    load_chunk(smb, 1, 1, b, r0, co_base, tid);

    for (int i = 0; i < 36; ++i) {
        if (i + 2 < 36) load_chunk(smb, (i + 2) % 3, i + 2, b, r0, co_base, tid);
        else CPCOMMIT();                       // keep group count in lockstep
        CPWAIT2();
        __syncthreads();

        const uint32_t stA = smb + (i % 3) * ST_SZ;
        const uint32_t stB = stA + 16384;
#pragma unroll
        for (int ks = 0; ks < 4; ++ks) {
            uint32_t a[4][4], bw[4][2];
#pragma unroll
            for (int mi = 0; mi < 4; ++mi) {
                uint32_t ad = stA + (rA + mi * 16) * 128
                            + (((ks * 2 + hiA) ^ sx) << 4);
                LDSM4(a[mi][0], a[mi][1], a[mi][2], a[mi][3], ad);
            }
#pragma unroll
            for (int g = 0; g < 2; ++g) {
                uint32_t bd = stB + (rB + g * 16) * 128
                            + (((ks * 2 + hiB) ^ sx) << 4);
                LDSM4(bw[2 * g][0], bw[2 * g][1], bw[2 * g + 1][0], bw[2 * g + 1][1], bd);
            }
#pragma unroll
            for (int mi = 0; mi < 4; ++mi)
#pragma unroll
                for (int ni = 0; ni < 4; ++ni)
                    MMA16816(c[mi][ni], a[mi], bw[ni][0], bw[ni][1]);
        }
        __syncthreads();
    }

    // ---- epilogue: regs -> smem transpose (pitch 129) -> fused stores ----
    float* smo = (float*)sm;
#pragma unroll
    for (int mi = 0; mi < 4; ++mi) {
        int row = mw * 64 + mi * 16 + (lane >> 2);
#pragma unroll
        for (int ni = 0; ni < 4; ++ni) {
            int col = nw * 32 + ni * 8 + 2 * (lane & 3);
            smo[row * 129 + col]           = c[mi][ni][0];
            smo[row * 129 + col + 1]       = c[mi][ni][1];
            smo[(row + 8) * 129 + col]     = c[mi][ni][2];
            smo[(row + 8) * 129 + col + 1] = c[mi][ni][3];
        }
    }
    __syncthreads();

    const int p = tid & 127;
    const int hrow = r0 + (p >> 6), wcol = p & 63;
    const float nz = noise[(b * HH + hrow) * WW + wcol] * nwp[0];
#pragma unroll 4
    for (int kk = 0; kk < 64; ++kk) {
        int co_l = (tid >> 7) + kk * 2;
        int co = co_base + co_l;
        float v = smo[p * 129 + co_l];
        v = v * g_d[b * COUT + co] + nz + bias[co];
        v = (v >= 0.f ? v : 0.2f * v) * 1.4142135623730951f;
        out[((size_t)(b * COUT + co) * HH + hrow) * WW + wcol] = v;
    }
}

// ---------------------------------------------------------------------------
extern "C" void kernel_launch(void* const* d_in, const int* in_sizes, int n_in,
                              void* d_out, int out_size) {
    const float* x       = (const float*)d_in[0];
    const float* style   = (const float*)d_in[1];
    const float* noise   = (const float*)d_in[2];
    const float* weight  = (const float*)d_in[3];
    const float* style_w = (const float*)d_in[4];
    const float* style_b = (const float*)d_in[5];
    const float* bias    = (const float*)d_in[6];
    const float* nw      = (const float*)d_in[7];
    float* out = (float*)d_out;

    cudaFuncSetAttribute(conv_mma_kernel,
                         cudaFuncAttributeMaxDynamicSharedMemorySize, SMEM_REQ);

    compute_s_kernel<<<BB, CIN>>>(style, style_w, style_b);
    wprep_kernel<<<COUT, CIN>>>(weight);
    compute_d_kernel<<<BB, COUT>>>();
    xconv_kernel<<<BB * HH, 256>>>((const float4*)x);
    conv_mma_kernel<<<dim3(HH / 2, COUT / 128, BB), 256, SMEM_REQ>>>(noise, bias, nw, out);
}

// round 10
// speedup vs baseline: 5.4693x; 1.0781x over previous
#include <cuda_runtime.h>
#include <cuda_fp16.h>
#include <cstdint>
#include <cstddef>

#define BB   16
#define CIN  256
#define COUT 256
#define HH   64
#define WW   64
#define LATD 512

typedef unsigned long long ull;

// ---------------- device scratch (no allocation allowed) ----------------
__device__ float g_s[BB * CIN];
__device__ float g_d[BB * COUT];
__device__ float g_w2[COUT * CIN];
// weights fp16, PRE-SWIZZLED (SW128 unit permutation): [tap][cic][co 0..255][64 ci]
__device__ __half g_wf[9 * 4 * 256 * 64];
// modulated x fp16, PRE-SWIZZLED, layout [cic][b][h][w][64ci], 128-half pad front+back
__device__ __half g_xa[(size_t)4 * BB * HH * WW * 64 + 256];
#define XA_BASE 64   // front pad (128B) so dx=-1 bulk reads stay in-array

// ---------------- prep kernels ----------------
__global__ void compute_s_kernel(const float* __restrict__ style,
                                 const float* __restrict__ style_w,
                                 const float* __restrict__ style_b) {
    int b = blockIdx.x, ci = threadIdx.x;
    float acc = style_b[ci];
    const float* srow = style + b * LATD;
#pragma unroll 4
    for (int l = 0; l < LATD; ++l)
        acc = fmaf(srow[l], style_w[l * CIN + ci], acc);
    g_s[b * CIN + ci] = acc;
}

__global__ void wprep_kernel(const float* __restrict__ weight) {
    int co = blockIdx.x, ci = threadIdx.x;
    const float* wp = weight + (co * CIN + ci) * 9;
    int cic = ci >> 6, cil = ci & 63;
    // swizzle: logical 16B unit u -> physical u ^ (co&7)
    int cil_sw = (((cil >> 3) ^ (co & 7)) << 3) | (cil & 7);
    float ssq = 0.f;
#pragma unroll
    for (int k = 0; k < 9; ++k) {
        float v = wp[k];
        ssq = fmaf(v, v, ssq);
        g_wf[((size_t)(k * 4 + cic) * 256 + co) * 64 + cil_sw] = __float2half_rn(v);
    }
    g_w2[co * CIN + ci] = ssq;
}

__global__ void compute_d_kernel() {
    int b = blockIdx.x, co = threadIdx.x;
    const float* srow = g_s + b * CIN;
    const float* w2row = g_w2 + co * CIN;
    float acc = 0.f;
#pragma unroll 4
    for (int ci = 0; ci < CIN; ++ci) {
        float s = srow[ci];
        acc = fmaf(s * s, w2row[ci], acc);
    }
    g_d[b * COUT + co] = rsqrtf(acc + 1e-8f);
}

// transpose + modulate + swizzle: x[b][ci][h][w] fp32 -> g_xa[cic][b][h][w][64ci] fp16
#define TP 266
__global__ void xconv_kernel(const float4* __restrict__ x4) {
    __shared__ unsigned short smt[64 * TP];
    int h = blockIdx.x & 63;
    int b = blockIdx.x >> 6;
    int t = threadIdx.x;
#pragma unroll
    for (int j = 0; j < 16; ++j) {
        int idx = t + 256 * j;               // 4096 float4 = 256ci * 16 w-groups
        int ci = idx >> 4;
        int g = idx & 15;
        float s = g_s[b * CIN + ci];
        float4 v = x4[((size_t)(b * CIN + ci) * HH + h) * 16 + g];
        int w = g * 4;
        smt[(w + 0) * TP + ci] = __half_as_ushort(__float2half_rn(v.x * s));
        smt[(w + 1) * TP + ci] = __half_as_ushort(__float2half_rn(v.y * s));
        smt[(w + 2) * TP + ci] = __half_as_ushort(__float2half_rn(v.z * s));
        smt[(w + 3) * TP + ci] = __half_as_ushort(__float2half_rn(v.w * s));
    }
    __syncthreads();
    // coalesced 128-bit writes, SW128 pre-swizzled: unit j -> j ^ (w&7)
    int w = t >> 2, q = t & 3;               // q = cic
    uint4* dst = (uint4*)(g_xa + XA_BASE +
        ((((size_t)q * BB + b) * HH + h) * WW + w) * 64);
    const int pw = w & 7;
#pragma unroll
    for (int j = 0; j < 8; ++j) {
        const uint32_t* p32 = (const uint32_t*)&smt[w * TP + q * 64 + j * 8];
        uint4 v;
        v.x = p32[0]; v.y = p32[1]; v.z = p32[2]; v.w = p32[3];
        dst[j ^ pw] = v;
    }
}

// ---------------- ptx helpers ----------------
static __device__ __forceinline__ uint32_t s2u(const void* p) {
    uint32_t a;
    asm("{ .reg .u64 t; cvta.to.shared.u64 t, %1; cvt.u32.u64 %0, t; }" : "=r"(a) : "l"(p));
    return a;
}
static __device__ __forceinline__ void mbar_init(uint32_t m, uint32_t c) {
    asm volatile("mbarrier.init.shared.b64 [%0], %1;" :: "r"(m), "r"(c) : "memory");
}
static __device__ __forceinline__ void mbar_expect(uint32_t m, uint32_t bytes) {
    asm volatile("mbarrier.arrive.expect_tx.shared.b64 _, [%0], %1;"
                 :: "r"(m), "r"(bytes) : "memory");
}
static __device__ __forceinline__ void mbar_wait(uint32_t m, uint32_t ph) {
    asm volatile(
        "{\n\t.reg .pred P;\n\t"
        "WL_%=:\n\t"
        "mbarrier.try_wait.parity.acquire.cta.shared::cta.b64 P, [%0], %1, 0x989680;\n\t"
        "@!P bra WL_%=;\n\t}"
        :: "r"(m), "r"(ph) : "memory");
}
static __device__ __forceinline__ void bulk_g2s(uint32_t dst, const void* src,
                                                uint32_t bytes, uint32_t mbar) {
    asm volatile(
        "cp.async.bulk.shared::cluster.global.mbarrier::complete_tx::bytes "
        "[%0], [%1], %2, [%3];"
        :: "r"(dst), "l"(src), "r"(bytes), "r"(mbar) : "memory");
}
#define LDSM4(r0, r1, r2, r3, a) \
    asm volatile("ldmatrix.sync.aligned.m8n8.x4.shared.b16 {%0,%1,%2,%3}, [%4];" \
                 : "=r"(r0), "=r"(r1), "=r"(r2), "=r"(r3) : "r"(a))
#define MMA16816(c, a, b0, b1) \
    asm volatile("mma.sync.aligned.m16n8k16.row.col.f32.f16.f16.f32 " \
                 "{%0,%1,%2,%3}, {%4,%5,%6,%7}, {%8,%9}, {%0,%1,%2,%3};" \
                 : "+f"((c)[0]), "+f"((c)[1]), "+f"((c)[2]), "+f"((c)[3]) \
                 : "r"((a)[0]), "r"((a)[1]), "r"((a)[2]), "r"((a)[3]), "r"(b0), "r"(b1))

// ---------------- main conv kernel ----------------
// smem: 3 stages x 32KB (A 16KB @ +0, B 16KB @ +16384); zero row; mbars.
#define ST_SZ    32768
#define SM_ZERO  (3 * ST_SZ)
#define SM_MBAR  (SM_ZERO + 128)
#define SMEM_REQ (SM_MBAR + 64)

// producer: one thread issues all async copies for chunk idx into stage st
static __device__ __forceinline__ void issue_chunk(uint32_t smb, int st, int idx,
                                                   int b, int r0, int co_base) {
    const int tap = idx >> 2, cic = idx & 3;
    const int dy = tap / 3 - 1, dx = tap % 3 - 1;
    const uint32_t base = smb + st * ST_SZ;
    const uint32_t mbar = smb + SM_MBAR + st * 8;
    const int v0 = (unsigned)(r0 + dy)     < 64u;
    const int v1 = (unsigned)(r0 + dy + 1) < 64u;
    mbar_expect(mbar, 16384u + (v0 ? 8192u : 0u) + (v1 ? 8192u : 0u));
    // B: 128 co rows x 64 ci, contiguous & pre-swizzled
    bulk_g2s(base + 16384, g_wf + ((size_t)(tap * 4 + cic) * 256 + co_base) * 64,
             16384u, mbar);
    // A: per h-row 64 pixels x 64 ci contiguous; dx = +-128B source offset
#pragma unroll
    for (int hh = 0; hh < 2; ++hh) {
        if (hh ? v1 : v0) {
            const __half* src = g_xa + XA_BASE +
                ((((size_t)cic * BB + b) * HH + (r0 + dy + hh)) * WW + dx) * 64;
            bulk_g2s(base + hh * 8192, src, 8192u, mbar);
        }
    }
}

__global__ void __launch_bounds__(256, 2) conv_mma_kernel(
    const float* __restrict__ noise,
    const float* __restrict__ bias,
    const float* __restrict__ nwp,
    float* __restrict__ out)
{
    extern __shared__ __align__(1024) char sm[];
    const uint32_t smb = s2u(sm);
    const int tid = threadIdx.x;
    const int lane = tid & 31, wid = tid >> 5;
    const int mw = wid & 1, nw = wid >> 1;
    const int r0 = blockIdx.x * 2;
    const int co_base = blockIdx.y * 128;
    const int b = blockIdx.z;

    // zero row + mbar init
    if (tid < 8) ((uint4*)(sm + SM_ZERO))[tid] = make_uint4(0, 0, 0, 0);
    if (tid == 0) {
        mbar_init(smb + SM_MBAR, 1);
        mbar_init(smb + SM_MBAR + 8, 1);
        mbar_init(smb + SM_MBAR + 16, 1);
    }
    __syncthreads();
    if (tid == 0) {
        issue_chunk(smb, 0, 0, b, r0, co_base);
        issue_chunk(smb, 1, 1, b, r0, co_base);
        issue_chunk(smb, 2, 2, b, r0, co_base);
    }

    // lane-constant pieces
    const int l15 = lane & 15;
    const int hiA = lane >> 4;
    const int rB = nw * 32 + (lane & 7) + ((lane >> 4) & 1) * 8;
    const int hiB = (lane >> 3) & 1;
    const int sx = lane & 7;

    float c[4][4][4] = {};
    int ph[3] = {0, 0, 0};

    for (int i = 0; i < 36; ++i) {
        const int s = i % 3;
        mbar_wait(smb + SM_MBAR + s * 8, ph[s]);
        ph[s] ^= 1;

        const uint32_t stA = smb + s * ST_SZ;
        const uint32_t stB = stA + 16384;

        // per-tap A row bases with OOB redirect to zero row
        const int tap = i >> 2;
        const int dy = tap / 3 - 1, dx = tap % 3 - 1;
        const int hv = (unsigned)(r0 + mw + dy) < 64u;
        uint32_t ab[4];
        int par[4];
#pragma unroll
        for (int mi = 0; mi < 4; ++mi) {
            int cA = mi * 16 + l15;          // output column 0..63
            int w = cA + dx;                  // source pixel column
            int val = hv && ((unsigned)w < 64u);
            ab[mi] = val ? (stA + (uint32_t)(mw * 64 + cA) * 128) : (smb + SM_ZERO);
            par[mi] = val ? (w & 7) : 0;
        }

#pragma unroll
        for (int ks = 0; ks < 4; ++ks) {
            uint32_t a[4][4], bw[4][2];
#pragma unroll
            for (int mi = 0; mi < 4; ++mi) {
                uint32_t ad = ab[mi] + (uint32_t)(((ks * 2 + hiA) ^ par[mi]) << 4);
                LDSM4(a[mi][0], a[mi][1], a[mi][2], a[mi][3], ad);
            }
#pragma unroll
            for (int g = 0; g < 2; ++g) {
                uint32_t bd = stB + (uint32_t)(rB + g * 16) * 128
                            + (uint32_t)(((ks * 2 + hiB) ^ sx) << 4);
                LDSM4(bw[2 * g][0], bw[2 * g][1], bw[2 * g + 1][0], bw[2 * g + 1][1], bd);
            }
#pragma unroll
            for (int mi = 0; mi < 4; ++mi)
#pragma unroll
                for (int ni = 0; ni < 4; ++ni)
                    MMA16816(c[mi][ni], a[mi], bw[ni][0], bw[ni][1]);
        }
        __syncthreads();                      // all reads of stage s done
        if (tid == 0 && i + 3 < 36)
            issue_chunk(smb, s, i + 3, b, r0, co_base);
    }

    // ---- epilogue: regs -> smem transpose (pitch 129) -> fused stores ----
    float* smo = (float*)sm;
#pragma unroll
    for (int mi = 0; mi < 4; ++mi) {
        int row = mw * 64 + mi * 16 + (lane >> 2);
#pragma unroll
        for (int ni = 0; ni < 4; ++ni) {
            int col = nw * 32 + ni * 8 + 2 * (lane & 3);
            smo[row * 129 + col]           = c[mi][ni][0];
            smo[row * 129 + col + 1]       = c[mi][ni][1];
            smo[(row + 8) * 129 + col]     = c[mi][ni][2];
            smo[(row + 8) * 129 + col + 1] = c[mi][ni][3];
        }
    }
    __syncthreads();

    const int p = tid & 127;
    const int hrow = r0 + (p >> 6), wcol = p & 63;
    const float nz = noise[(b * HH + hrow) * WW + wcol] * nwp[0];
#pragma unroll 4
    for (int kk = 0; kk < 64; ++kk) {
        int co_l = (tid >> 7) + kk * 2;
        int co = co_base + co_l;
        float v = smo[p * 129 + co_l];
        v = v * g_d[b * COUT + co] + nz + bias[co];
        v = (v >= 0.f ? v : 0.2f * v) * 1.4142135623730951f;
        out[((size_t)(b * COUT + co) * HH + hrow) * WW + wcol] = v;
    }
}

// ---------------------------------------------------------------------------
extern "C" void kernel_launch(void* const* d_in, const int* in_sizes, int n_in,
                              void* d_out, int out_size) {
    const float* x       = (const float*)d_in[0];
    const float* style   = (const float*)d_in[1];
    const float* noise   = (const float*)d_in[2];
    const float* weight  = (const float*)d_in[3];
    const float* style_w = (const float*)d_in[4];
    const float* style_b = (const float*)d_in[5];
    const float* bias    = (const float*)d_in[6];
    const float* nw      = (const float*)d_in[7];
    float* out = (float*)d_out;

    cudaFuncSetAttribute(conv_mma_kernel,
                         cudaFuncAttributeMaxDynamicSharedMemorySize, SMEM_REQ);

    compute_s_kernel<<<BB, CIN>>>(style, style_w, style_b);
    wprep_kernel<<<COUT, CIN>>>(weight);
    compute_d_kernel<<<BB, COUT>>>();
    xconv_kernel<<<BB * HH, 256>>>((const float4*)x);
    conv_mma_kernel<<<dim3(HH / 2, COUT / 128, BB), 256, SMEM_REQ>>>(noise, bias, nw, out);
}